// round 7
// baseline (speedup 1.0000x reference)
#include <cuda_runtime.h>
#include <cuda_fp16.h>
#include <math.h>
#include <cstdint>

// ---------------------------------------------------------------------------
// VectorQuantizerEMA: N=32768 vectors, D=256, K=8192 codes
// FP16 mma.sync argmin + exact fp64 top-4 rerank + sort-based EMA update.
// d_out layout (float32):
//   [0)          out (quant_st NCHW) 8388608
//   [8388608)    loss 1
//   [8388609)    perplexity 1
//   [8388610)    new_cluster_size 8192
//   [8396802)    new_embed 2097152
//   [10493954)   new_ema_embed 2097152
// ---------------------------------------------------------------------------

#define NB      32
#define DD      256
#define HW      1024
#define NN      32768
#define KK      8192

#define OUT_OFF      0
#define LOSS_OFF     8388608
#define PERP_OFF     8388609
#define NCS_OFF      8388610
#define NEWEMB_OFF   8396802
#define NEWEMA_OFF   10493954

#define KSPLIT  8
#define KPS     (KK / KSPLIT)     // 1024 codes per slice
#define KSLOT   (KSPLIT * 4)      // 32 disjoint candidate slots per row

// ---- scratch (device globals; no allocation allowed) ----
__device__ float   g_X[NN * DD];      // fp32 transposed inputs [N,D]
__device__ __half  g_Xf[NN * DD];     // fp16 [N,D]
__device__ float   g_EtF[KK * DD];    // fp32 E^T [K,D]
__device__ __half  g_Ef[KK * DD];     // fp16 E^T [K,D]
__device__ float   g_dwT[KK * DD];    // segment sums [K,D]
__device__ float g_enorm[KK];
__device__ int   g_idx[NN];
__device__ int   g_cand[NN * 4];
__device__ float g_sv1[NN * KSLOT];
__device__ float g_sv2[NN * KSLOT];
__device__ int   g_si1[NN * KSLOT];
__device__ int   g_si2[NN * KSLOT];
__device__ int   g_icnt[KK];
__device__ int   g_codeoff[KK];
__device__ int   g_cursor[KK];
__device__ int   g_order[NN];
__device__ float g_invsm[KK];
__device__ float g_scal[4];

// ===========================================================================
// helpers
// ===========================================================================
__device__ __forceinline__ uint32_t smem_to_u32(const void* p) {
    uint32_t a;
    asm("{ .reg .u64 t; cvta.to.shared.u64 t, %1; cvt.u32.u64 %0, t; }"
        : "=r"(a) : "l"(p));
    return a;
}
__device__ __forceinline__ void ldsm4(uint32_t* r, uint32_t addr) {
    asm volatile("ldmatrix.sync.aligned.m8n8.x4.shared.b16 {%0,%1,%2,%3}, [%4];"
                 : "=r"(r[0]), "=r"(r[1]), "=r"(r[2]), "=r"(r[3]) : "r"(addr));
}
__device__ __forceinline__ void mma16816(float* c, const uint32_t* a, const uint32_t* b) {
    asm volatile(
        "mma.sync.aligned.m16n8k16.row.col.f32.f16.f16.f32 "
        "{%0,%1,%2,%3}, {%4,%5,%6,%7}, {%8,%9}, {%0,%1,%2,%3};"
        : "+f"(c[0]), "+f"(c[1]), "+f"(c[2]), "+f"(c[3])
        : "r"(a[0]), "r"(a[1]), "r"(a[2]), "r"(a[3]), "r"(b[0]), "r"(b[1]));
}
__device__ __forceinline__ void cp16(uint32_t dst, const void* src) {
    asm volatile("cp.async.cg.shared.global [%0], [%1], 16;"
                 :: "r"(dst), "l"(src) : "memory");
}
#define CP_COMMIT() asm volatile("cp.async.commit_group;" ::: "memory")

// smem: A [kc(4)][128 rows][128B swizzled] = 64KB ; B [buf(2)][128 codes][128B] = 32KB
#define SMEM_A   0
#define SMEM_B   65536
#define SMEM_TOT 98304

// ---------------------------------------------------------------------------
// K0: NCHW -> [N,D]; fp32 + fp16
// ---------------------------------------------------------------------------
__global__ void transpose_kernel(const float* __restrict__ in) {
    __shared__ float tile[32][33];
    int b  = blockIdx.z;
    int d0 = blockIdx.y * 32;
    int h0 = blockIdx.x * 32;
    int tx = threadIdx.x, ty = threadIdx.y;   // 32 x 8
    const float* src = in + (size_t)b * DD * HW;
#pragma unroll
    for (int i = 0; i < 32; i += 8)
        tile[ty + i][tx] = src[(d0 + ty + i) * HW + h0 + tx];
    __syncthreads();
#pragma unroll
    for (int i = 0; i < 32; i += 8) {
        float v = tile[tx][ty + i];
        size_t o = (size_t)(b * HW + h0 + ty + i) * DD + d0 + tx;
        g_X[o]  = v;
        g_Xf[o] = __float2half_rn(v);
    }
}

// ---------------------------------------------------------------------------
// K0b: embed [D,K] -> E^T [K,D] fp32 + fp16
// ---------------------------------------------------------------------------
__global__ void etrans_kernel(const float* __restrict__ embed) {
    __shared__ float tile[32][33];
    int k0 = blockIdx.x * 32;
    int d0 = blockIdx.y * 32;
    int tx = threadIdx.x, ty = threadIdx.y;   // 32 x 8
#pragma unroll
    for (int i = 0; i < 32; i += 8)
        tile[ty + i][tx] = embed[(size_t)(d0 + ty + i) * KK + k0 + tx];
    __syncthreads();
#pragma unroll
    for (int i = 0; i < 32; i += 8) {
        float v = tile[tx][ty + i];
        size_t o = (size_t)(k0 + ty + i) * DD + d0 + tx;
        g_EtF[o] = v;
        g_Ef[o]  = __float2half_rn(v);
    }
}

// ---------------------------------------------------------------------------
// K1: ||e_k||^2 (fp32 exact)
// ---------------------------------------------------------------------------
__global__ void enorm_kernel(const float* __restrict__ embed) {
    int k = blockIdx.x * 256 + threadIdx.x;
    float s = 0.f;
#pragma unroll 8
    for (int d = 0; d < DD; d++) {
        float v = embed[(size_t)d * KK + k];
        s = fmaf(v, v, s);
    }
    g_enorm[k] = s;
}

// ---------------------------------------------------------------------------
// K1b: zero counters
// ---------------------------------------------------------------------------
__global__ void zero_kernel() {
    int i = blockIdx.x * 256 + threadIdx.x;
    if (i < KK) g_icnt[i] = 0;
    if (i < 4)  g_scal[i] = 0.f;
}

// ---------------------------------------------------------------------------
// B-chunk producer: 128 codes x 64 d (fp16) via cp.async into buffer `buf`
// ---------------------------------------------------------------------------
__device__ __forceinline__ void issueB(uint32_t sb, int buf, int c0, int kc, int tid) {
#pragma unroll
    for (int i = 0; i < 4; ++i) {
        int v = tid + i * 256;            // 0..1023
        int code = v >> 3, g = v & 7;
        const void* s = &g_Ef[(size_t)(c0 + code) * DD + kc * 64 + g * 8];
        uint32_t d = sb + SMEM_B + buf * 16384 + code * 128
                   + (uint32_t)((g ^ (code & 7)) << 4);
        cp16(d, s);
    }
    CP_COMMIT();
}

// ---------------------------------------------------------------------------
// K2: fp16 mma.sync argmin. CTA = 128 rows x 1024-code slice. 8 warps (2x4).
// ---------------------------------------------------------------------------
__global__ __launch_bounds__(256, 2) void argmin_mma_kernel() {
    extern __shared__ char smem[];
    uint32_t sb = smem_to_u32(smem);
    int tid  = threadIdx.x;
    int lane = tid & 31, wid = tid >> 5;
    int wm = wid >> 2, wn = wid & 3;
    int mt = blockIdx.x >> 3, slice = blockIdx.x & 7;
    int n0 = mt * 128;
    int cs0 = slice * KPS;

    // ---- stage A (resident): 128 rows x 256 d fp16, swizzled ----
#pragma unroll
    for (int i = 0; i < 16; ++i) {
        int v = tid + i * 256;            // 0..4095
        int kc = v >> 10;
        int u = v & 1023;
        int row = u >> 3, g = u & 7;
        uint32_t off = SMEM_A + kc * 16384 + row * 128
                     + (uint32_t)((g ^ (row & 7)) << 4);
        *(uint4*)(smem + off) =
            *(const uint4*)&g_Xf[(size_t)(n0 + row) * DD + kc * 64 + g * 8];
    }

    // ---- prologue: prefetch B chunks 0,1 ----
    issueB(sb, 0, cs0, 0, tid);
    issueB(sb, 1, cs0, 1, tid);

    float acc[4][4][4];
#pragma unroll
    for (int m = 0; m < 4; ++m)
#pragma unroll
        for (int n = 0; n < 4; ++n)
#pragma unroll
            for (int q = 0; q < 4; ++q) acc[m][n][q] = 0.f;

    float t1v[8], t2v[8];
    int   t1i[8], t2i[8];
#pragma unroll
    for (int s = 0; s < 8; ++s) { t1v[s] = 3.4e38f; t2v[s] = 3.4e38f; t1i[s] = 0; t2i[s] = 0; }

    // per-lane ldmatrix address components
    int j   = lane >> 3, rwi = lane & 7;
    int arow = wm * 64 + rwi + ((j & 1) << 3);
    int agsel = j >> 1;
    int arx  = arow & 7;
    uint32_t aBase = sb + SMEM_A + (uint32_t)arow * 128;
    int crow = wn * 32 + ((j >> 1) << 3) + rwi;
    int bgsel = j & 1;
    int crx  = crow & 7;
    uint32_t bBase = sb + SMEM_B + (uint32_t)crow * 128;

    int tid4 = lane & 3;

#pragma unroll 1
    for (int it = 0; it < KPS / 32; ++it) {       // 32 iters
        int kc = it & 3, buf = it & 1;
        if (it < KPS / 32 - 1) asm volatile("cp.async.wait_group 1;" ::: "memory");
        else                   asm volatile("cp.async.wait_group 0;" ::: "memory");
        __syncthreads();

#pragma unroll
        for (int kk = 0; kk < 4; ++kk) {
            uint32_t ah[4][4], bh[2][4];
            uint32_t ga = (uint32_t)(((2 * kk + agsel) ^ arx) << 4);
            uint32_t gb = (uint32_t)(((2 * kk + bgsel) ^ crx) << 4);
#pragma unroll
            for (int m = 0; m < 4; ++m)
                ldsm4(ah[m], aBase + kc * 16384 + m * 2048 + ga);
#pragma unroll
            for (int np = 0; np < 2; ++np)
                ldsm4(bh[np], bBase + buf * 16384 + np * 2048 + gb);
#pragma unroll
            for (int m = 0; m < 4; ++m)
#pragma unroll
                for (int n = 0; n < 4; ++n)
                    mma16816(acc[m][n], ah[m], &bh[n >> 1][(n & 1) * 2]);
        }
        __syncthreads();
        if (it + 2 < KPS / 32) {
            int it2 = it + 2;
            issueB(sb, it2 & 1, cs0 + (it2 >> 2) * 128, it2 & 3, tid);
        }

        if (kc == 3) {
            int nt = it >> 2;
            int cb = cs0 + nt * 128 + wn * 32 + tid4 * 2;
#pragma unroll
            for (int m = 0; m < 4; ++m) {
#pragma unroll
                for (int n = 0; n < 4; ++n) {
                    int c = cb + n * 8;
                    float2 en = *(const float2*)&g_enorm[c];
                    float d0 = fmaf(-2.f, acc[m][n][0], en.x);
                    float d1 = fmaf(-2.f, acc[m][n][1], en.y);
                    float d2 = fmaf(-2.f, acc[m][n][2], en.x);
                    float d3 = fmaf(-2.f, acc[m][n][3], en.y);
                    int s0 = m * 2, s1 = m * 2 + 1;
                    if (d0 < t1v[s0]) { t2v[s0] = t1v[s0]; t2i[s0] = t1i[s0]; t1v[s0] = d0; t1i[s0] = c; }
                    else if (d0 < t2v[s0]) { t2v[s0] = d0; t2i[s0] = c; }
                    if (d1 < t1v[s0]) { t2v[s0] = t1v[s0]; t2i[s0] = t1i[s0]; t1v[s0] = d1; t1i[s0] = c + 1; }
                    else if (d1 < t2v[s0]) { t2v[s0] = d1; t2i[s0] = c + 1; }
                    if (d2 < t1v[s1]) { t2v[s1] = t1v[s1]; t2i[s1] = t1i[s1]; t1v[s1] = d2; t1i[s1] = c; }
                    else if (d2 < t2v[s1]) { t2v[s1] = d2; t2i[s1] = c; }
                    if (d3 < t1v[s1]) { t2v[s1] = t1v[s1]; t2i[s1] = t1i[s1]; t1v[s1] = d3; t1i[s1] = c + 1; }
                    else if (d3 < t2v[s1]) { t2v[s1] = d3; t2i[s1] = c + 1; }
#pragma unroll
                    for (int q = 0; q < 4; ++q) acc[m][n][q] = 0.f;
                }
            }
        }
    }

    // ---- merge top-2 across the 4 threads that share each row ----
#pragma unroll
    for (int s = 0; s < 8; ++s) {
        float v1 = t1v[s], v2 = t2v[s];
        int   i1 = t1i[s], i2 = t2i[s];
#pragma unroll
        for (int off = 1; off <= 2; off <<= 1) {
            float ov1 = __shfl_xor_sync(0xffffffffu, v1, off);
            int   oi1 = __shfl_xor_sync(0xffffffffu, i1, off);
            float ov2 = __shfl_xor_sync(0xffffffffu, v2, off);
            int   oi2 = __shfl_xor_sync(0xffffffffu, i2, off);
            if (ov1 < v1 || (ov1 == v1 && oi1 < i1)) {
                float nv2; int ni2;
                if (v1 < ov2 || (v1 == ov2 && i1 < oi2)) { nv2 = v1; ni2 = i1; }
                else { nv2 = ov2; ni2 = oi2; }
                v1 = ov1; i1 = oi1; v2 = nv2; i2 = ni2;
            } else {
                if (ov1 < v2 || (ov1 == v2 && oi1 < i2)) { v2 = ov1; i2 = oi1; }
            }
        }
        if (tid4 == 0) {
            int grp = lane >> 2;
            int row = n0 + wm * 64 + (s >> 1) * 16 + (s & 1) * 8 + grp;
            int slot = slice * 4 + wn;          // disjoint code subset per slot
            g_sv1[row * KSLOT + slot] = v1;
            g_si1[row * KSLOT + slot] = i1;
            g_sv2[row * KSLOT + slot] = v2;
            g_si2[row * KSLOT + slot] = i2;
        }
    }
}

// ---------------------------------------------------------------------------
// K2b: merge 32 slots (64 candidates) -> global top-4 per row
// ---------------------------------------------------------------------------
__device__ __forceinline__ void ins4(float* bv, int* bi, float v, int i) {
#pragma unroll
    for (int s = 0; s < 4; ++s) {
        if (v < bv[s] || (v == bv[s] && i < bi[s])) {
            for (int q = 3; q > s; --q) { bv[q] = bv[q - 1]; bi[q] = bi[q - 1]; }
            bv[s] = v; bi[s] = i;
            return;
        }
    }
}

__global__ void merge_kernel() {
    int row = blockIdx.x * 256 + threadIdx.x;
    float bv[4] = {3.4e38f, 3.4e38f, 3.4e38f, 3.4e38f};
    int   bi[4] = {0, 0, 0, 0};
#pragma unroll
    for (int s = 0; s < KSLOT; ++s) {
        ins4(bv, bi, g_sv1[row * KSLOT + s], g_si1[row * KSLOT + s]);
        ins4(bv, bi, g_sv2[row * KSLOT + s], g_si2[row * KSLOT + s]);
    }
#pragma unroll
    for (int c = 0; c < 4; ++c) g_cand[row * 4 + c] = bi[c];
}

// ---------------------------------------------------------------------------
// K2c: exact fp64 rerank of 4 candidates per row (1 warp per row)
// ---------------------------------------------------------------------------
__global__ void rerank_kernel() {
    int row = blockIdx.x * 8 + (threadIdx.x >> 5);
    int lane = threadIdx.x & 31;
    const float4* xp = (const float4*)&g_X[(size_t)row * DD + lane * 8];
    float4 xa = xp[0], xb = xp[1];
    double s[4];
#pragma unroll
    for (int c = 0; c < 4; ++c) {
        int cd = g_cand[row * 4 + c];
        const float4* ep = (const float4*)&g_EtF[(size_t)cd * DD + lane * 8];
        float4 ea = ep[0], eb = ep[1];
        double t, acc = 0.0;
        t = (double)xa.x - ea.x; acc += t * t;
        t = (double)xa.y - ea.y; acc += t * t;
        t = (double)xa.z - ea.z; acc += t * t;
        t = (double)xa.w - ea.w; acc += t * t;
        t = (double)xb.x - eb.x; acc += t * t;
        t = (double)xb.y - eb.y; acc += t * t;
        t = (double)xb.z - eb.z; acc += t * t;
        t = (double)xb.w - eb.w; acc += t * t;
        s[c] = acc;
    }
#pragma unroll
    for (int o = 16; o; o >>= 1) {
#pragma unroll
        for (int c = 0; c < 4; ++c)
            s[c] += __shfl_down_sync(0xffffffffu, s[c], o);
    }
    if (lane == 0) {
        double bv = s[0]; int bi = g_cand[row * 4];
#pragma unroll
        for (int c = 1; c < 4; ++c) {
            int cd = g_cand[row * 4 + c];
            if (s[c] < bv || (s[c] == bv && cd < bi)) { bv = s[c]; bi = cd; }
        }
        g_idx[row] = bi;
    }
}

// ---------------------------------------------------------------------------
// K3a: histogram of code assignments
// ---------------------------------------------------------------------------
__global__ void hist_kernel() {
    int n = blockIdx.x * 256 + threadIdx.x;
    atomicAdd(&g_icnt[g_idx[n]], 1);
}

// ---------------------------------------------------------------------------
// K3b: exclusive scan of 8192 counts (single block, 1024 threads x 8)
// ---------------------------------------------------------------------------
__global__ void scan_kernel() {
    __shared__ int wsum[32];
    int t = threadIdx.x;
    int lane = t & 31, wid = t >> 5;
    int v[8], pre[8], s = 0;
#pragma unroll
    for (int i = 0; i < 8; ++i) {
        v[i] = g_icnt[t * 8 + i];
        pre[i] = s;
        s += v[i];
    }
    int ps = s;
#pragma unroll
    for (int o = 1; o < 32; o <<= 1) {
        int u = __shfl_up_sync(0xffffffffu, ps, o);
        if (lane >= o) ps += u;
    }
    if (lane == 31) wsum[wid] = ps;
    int excl_in_warp = ps - s;
    __syncthreads();
    if (wid == 0) {
        int w = wsum[lane];
        int orig = w;
#pragma unroll
        for (int o = 1; o < 32; o <<= 1) {
            int u = __shfl_up_sync(0xffffffffu, w, o);
            if (lane >= o) w += u;
        }
        wsum[lane] = w - orig;
    }
    __syncthreads();
    int base = wsum[wid] + excl_in_warp;
#pragma unroll
    for (int i = 0; i < 8; ++i) {
        int off = base + pre[i];
        g_codeoff[t * 8 + i] = off;
        g_cursor[t * 8 + i]  = off;
    }
}

// ---------------------------------------------------------------------------
// K3c: place row ids into code-sorted order
// ---------------------------------------------------------------------------
__global__ void place_kernel() {
    int n = blockIdx.x * 256 + threadIdx.x;
    int pos = atomicAdd(&g_cursor[g_idx[n]], 1);
    g_order[pos] = n;
}

// ---------------------------------------------------------------------------
// K3d: per-code segment sum into dwT [K,D] (no atomics)
// ---------------------------------------------------------------------------
__global__ __launch_bounds__(64) void accum_kernel() {
    int k = blockIdx.x;
    int t = threadIdx.x;          // 64 threads x float4 = 256 dims
    int cnt = g_icnt[k];
    int off = g_codeoff[k];
    float4 acc = make_float4(0.f, 0.f, 0.f, 0.f);
    for (int i = 0; i < cnt; ++i) {
        int n = g_order[off + i];
        float4 v = *(const float4*)&g_X[(size_t)n * DD + t * 4];
        acc.x += v.x; acc.y += v.y; acc.z += v.z; acc.w += v.w;
    }
    *(float4*)&g_dwT[(size_t)k * DD + t * 4] = acc;
}

// ---------------------------------------------------------------------------
// K4: gather quantize -> out (NCHW), accumulate e_latent_loss
// ---------------------------------------------------------------------------
__global__ void gather_kernel(const float* __restrict__ inputs,
                              const float* __restrict__ embed,
                              float* __restrict__ out) {
    __shared__ int sidx[HW];
    __shared__ float sred[8];
    int b  = blockIdx.x >> 3;
    int d0 = (blockIdx.x & 7) * 32;
    int t  = threadIdx.x;

    for (int i = t; i < HW; i += 256) sidx[i] = g_idx[b * HW + i];
    __syncthreads();

    float lsum = 0.f;
    for (int d = d0; d < d0 + 32; d++) {
        const float* erow = embed + (size_t)d * KK;
        const float* irow = inputs + (size_t)b * DD * HW + (size_t)d * HW;
        float* orow       = out + OUT_OFF + (size_t)b * DD * HW + (size_t)d * HW;
#pragma unroll
        for (int hw = t; hw < HW; hw += 256) {
            float q = erow[sidx[hw]];
            float x = irow[hw];
            orow[hw] = q;
            float df = q - x;
            lsum = fmaf(df, df, lsum);
        }
    }
#pragma unroll
    for (int o = 16; o; o >>= 1) lsum += __shfl_down_sync(0xffffffffu, lsum, o);
    if ((t & 31) == 0) sred[t >> 5] = lsum;
    __syncthreads();
    if (t == 0) {
        float s = 0.f;
#pragma unroll
        for (int i = 0; i < 8; i++) s += sred[i];
        atomicAdd(&g_scal[0], s);
    }
}

// ---------------------------------------------------------------------------
// K6: finalize scalars + new_cluster_size + 1/smoothed
// ---------------------------------------------------------------------------
__global__ void finalize_kernel(const float* __restrict__ cs, float* __restrict__ out) {
    __shared__ float sh[32];
    __shared__ float s_n;
    int t = threadIdx.x;
    float ncs_loc[8];
    float nsum = 0.f, psum = 0.f;
#pragma unroll
    for (int i = 0; i < 8; i++) {
        int k = t + i * 1024;
        float c = (float)g_icnt[k];
        float v = cs[k] * 0.99f + 0.01f * c;
        out[NCS_OFF + k] = v;
        ncs_loc[i] = v;
        nsum += v;
        float p = c * (1.0f / 32768.0f);
        psum += p * logf(p + 1e-10f);
    }
#pragma unroll
    for (int o = 16; o; o >>= 1) nsum += __shfl_down_sync(0xffffffffu, nsum, o);
    if ((t & 31) == 0) sh[t >> 5] = nsum;
    __syncthreads();
    if (t < 32) {
        float v = sh[t];
#pragma unroll
        for (int o = 16; o; o >>= 1) v += __shfl_down_sync(0xffffffffu, v, o);
        if (t == 0) s_n = v;
    }
    __syncthreads();
    float n = s_n;
#pragma unroll
    for (int i = 0; i < 8; i++) {
        int k = t + i * 1024;
        float v = ncs_loc[i];
        g_invsm[k] = (n + v * 1e-5f) / (n * (v + 1e-5f));
    }
    __syncthreads();
#pragma unroll
    for (int o = 16; o; o >>= 1) psum += __shfl_down_sync(0xffffffffu, psum, o);
    if ((t & 31) == 0) sh[t >> 5] = psum;
    __syncthreads();
    if (t == 0) {
        float p = 0.f;
#pragma unroll
        for (int i = 0; i < 32; i++) p += sh[i];
        out[LOSS_OFF] = 0.25f * g_scal[0] * (1.0f / 8388608.0f);
        out[PERP_OFF] = expf(-p);
    }
}

// ---------------------------------------------------------------------------
// K7: new_ema = 0.99 ema + 0.01 dw ; new_embed = new_ema * invsm
// dwT is [K,D]; outputs are [D,K]. smem tile transpose, coalesced both sides.
// ---------------------------------------------------------------------------
__global__ void emafinal_kernel(const float* __restrict__ ema, float* __restrict__ out) {
    __shared__ float tile[32][33];
    int k0 = blockIdx.x * 32;
    int d0 = blockIdx.y * 32;
    int tx = threadIdx.x, ty = threadIdx.y;   // 32 x 8
#pragma unroll
    for (int i = 0; i < 32; i += 8)
        tile[ty + i][tx] = g_dwT[(size_t)(k0 + ty + i) * DD + d0 + tx];
    __syncthreads();
    float inv = g_invsm[k0 + tx];
#pragma unroll
    for (int i = 0; i < 32; i += 8) {
        size_t o = (size_t)(d0 + ty + i) * KK + k0 + tx;
        float nm = 0.99f * ema[o] + 0.01f * tile[tx][ty + i];
        out[NEWEMA_OFF + o] = nm;
        out[NEWEMB_OFF + o] = nm * inv;
    }
}

// ---------------------------------------------------------------------------
extern "C" void kernel_launch(void* const* d_in, const int* in_sizes, int n_in,
                              void* d_out, int out_size) {
    const float* inputs = (const float*)d_in[0];
    const float* embed  = (const float*)d_in[1];
    const float* cs     = (const float*)d_in[2];
    const float* ema    = (const float*)d_in[3];
    float* out = (float*)d_out;
    (void)in_sizes; (void)n_in; (void)out_size;

    cudaFuncSetAttribute(argmin_mma_kernel,
                         cudaFuncAttributeMaxDynamicSharedMemorySize, SMEM_TOT);

    transpose_kernel<<<dim3(32, 8, 32), dim3(32, 8)>>>(inputs);
    etrans_kernel<<<dim3(KK / 32, DD / 32), dim3(32, 8)>>>(embed);
    enorm_kernel<<<KK / 256, 256>>>(embed);
    zero_kernel<<<KK / 256, 256>>>();
    argmin_mma_kernel<<<(NN / 128) * KSPLIT, 256, SMEM_TOT>>>();
    merge_kernel<<<NN / 256, 256>>>();
    rerank_kernel<<<NN / 8, 256>>>();
    hist_kernel<<<NN / 256, 256>>>();
    scan_kernel<<<1, 1024>>>();
    place_kernel<<<NN / 256, 256>>>();
    accum_kernel<<<KK, 64>>>();
    gather_kernel<<<256, 256>>>(inputs, embed, out);
    finalize_kernel<<<1, 1024>>>(cs, out);
    emafinal_kernel<<<dim3(KK / 32, DD / 32), dim3(32, 8)>>>(ema, out);
}